// round 1
// baseline (speedup 1.0000x reference)
#include <cuda_runtime.h>

// Problem constants (fixed by the dataset)
#define NMAX 50000
#define EMAX 800000
#define D    64
#define D2   32

// ---------------- scratch (device globals; no runtime allocation) -----------
__device__ float d_buf0[NMAX * D];
__device__ float d_buf1[NMAX * D];
__device__ float d_acc [NMAX * D];
__device__ float d_g   [NMAX * D];   // conv1: xs @ W_lin1
__device__ float d_hid [NMAX * D];   // conv1 output (post relu)
__device__ float d_g2  [NMAX * D2];  // conv2: h1 @ W_lin2
__device__ float d_p   [NMAX];
__device__ float d_q   [NMAX];
__device__ float d_invdeg[NMAX];
__device__ int   d_cnt [NMAX];
__device__ int   d_rowptr[NMAX + 1];
__device__ int   d_cursor[NMAX];
__device__ int   d_col [EMAX];
__device__ int   d_bsum[256];

// ---------------- CSR build --------------------------------------------------
__global__ void k_zero_cnt(int n) {
    int i = blockIdx.x * blockDim.x + threadIdx.x;
    if (i < n) d_cnt[i] = 0;
}

__global__ void k_count(const int* __restrict__ dst, int e) {
    for (int i = blockIdx.x * blockDim.x + threadIdx.x; i < e;
         i += gridDim.x * blockDim.x)
        atomicAdd(&d_cnt[dst[i]], 1);
}

// Block-local exclusive scan (512/block) of d_cnt -> d_rowptr, block sums -> d_bsum
__global__ void k_scanA(int n) {
    __shared__ int sh[512];
    int i = blockIdx.x * 512 + threadIdx.x;
    int v = (i < n) ? d_cnt[i] : 0;
    sh[threadIdx.x] = v;
    __syncthreads();
#pragma unroll
    for (int off = 1; off < 512; off <<= 1) {
        int t = (threadIdx.x >= off) ? sh[threadIdx.x - off] : 0;
        __syncthreads();
        sh[threadIdx.x] += t;
        __syncthreads();
    }
    if (i < n) d_rowptr[i] = sh[threadIdx.x] - v;  // exclusive within block
    if (threadIdx.x == 511) d_bsum[blockIdx.x] = sh[511];
}

__global__ void k_scanB(int nb) {  // <<<1,1>>> — nb <= 98, trivial
    int run = 0;
    for (int b = 0; b < nb; b++) { int t = d_bsum[b]; d_bsum[b] = run; run += t; }
}

__global__ void k_scanC(int n, int e) {
    int i = blockIdx.x * blockDim.x + threadIdx.x;
    if (i >= n) return;
    int rp = d_rowptr[i] + d_bsum[i >> 9];
    d_rowptr[i] = rp;
    d_cursor[i] = rp;
    int c = d_cnt[i];
    d_invdeg[i] = 1.0f / (float)(c > 1 ? c : 1);
    if (i == 0) d_rowptr[n] = e;
}

__global__ void k_fill(const int* __restrict__ src, const int* __restrict__ dst, int e) {
    for (int i = blockIdx.x * blockDim.x + threadIdx.x; i < e;
         i += gridDim.x * blockDim.x) {
        int dd  = dst[i];
        int pos = atomicAdd(&d_cursor[dd], 1);
        d_col[pos] = src[i];
    }
}

// ---------------- smoothing pass: hout = mean_in(hin); acc (+)= hout ---------
__global__ void k_pass(const float* __restrict__ hin, float* __restrict__ hout,
                       int init, int n) {
    int w    = (blockIdx.x * blockDim.x + threadIdx.x) >> 5;
    int lane = threadIdx.x & 31;
    if (w >= n) return;
    int beg = d_rowptr[w], end = d_rowptr[w + 1];
    float a0 = 0.f, a1 = 0.f;
    for (int ei = beg; ei < end; ei++) {
        int s = d_col[ei];
        a0 += hin[s * D + lane];
        a1 += hin[s * D + lane + 32];
    }
    float inv = d_invdeg[w];
    a0 *= inv; a1 *= inv;
    hout[w * D + lane]      = a0;
    hout[w * D + lane + 32] = a1;
    if (init) {  // hin == x on the first pass: acc = x + mean
        d_acc[w * D + lane]      = hin[w * D + lane]      + a0;
        d_acc[w * D + lane + 32] = hin[w * D + lane + 32] + a1;
    } else {
        d_acc[w * D + lane]      += a0;
        d_acc[w * D + lane + 32] += a1;
    }
}

// ---------------- node GEMM: out[n,M] = (hin[n,64]*scale) @ W[64,M] ----------
template <int M>
__global__ void k_gemm(const float* __restrict__ hin, float scale,
                       const float* __restrict__ W, float* __restrict__ out, int n) {
    constexpr int NPG = 128 / M;                 // nodes per group
    __shared__ float Wsh[64 * M];
    __shared__ float xr[NPG][64];
    int o  = threadIdx.x % M;
    int ln = threadIdx.x / M;
    for (int idx = threadIdx.x; idx < 64 * M; idx += 128) Wsh[idx] = W[idx];
    __syncthreads();
    for (int base = blockIdx.x * NPG; base < n; base += gridDim.x * NPG) {
        int node = base + ln;
        if (node < n)
            for (int k = o; k < 64; k += M) xr[ln][k] = hin[node * 64 + k] * scale;
        __syncthreads();
        if (node < n) {
            float acc = 0.f;
#pragma unroll
            for (int k = 0; k < 64; k++) acc += xr[ln][k] * Wsh[k * M + o];
            out[node * M + o] = acc;
        }
        __syncthreads();
    }
}

// ---------------- p/q per node: p = h·a[:64], q = h·a[64:128] ---------------
__global__ void k_pq(const float* __restrict__ hin, float scale,
                     const float* __restrict__ Watt,
                     float* __restrict__ p, float* __restrict__ q, int n) {
    int w    = (blockIdx.x * blockDim.x + threadIdx.x) >> 5;
    int lane = threadIdx.x & 31;
    if (w >= n) return;
    float x0 = hin[w * 64 + lane] * scale;
    float x1 = hin[w * 64 + lane + 32] * scale;
    float pp = x0 * Watt[lane]      + x1 * Watt[lane + 32];
    float qq = x0 * Watt[64 + lane] + x1 * Watt[96 + lane];
#pragma unroll
    for (int off = 16; off; off >>= 1) {
        pp += __shfl_down_sync(0xffffffffu, pp, off);
        qq += __shfl_down_sync(0xffffffffu, qq, off);
    }
    if (lane == 0) { p[w] = pp; q[w] = qq; }
}

// ---------------- conv edge aggregation, 64-wide output (conv1, + relu) ------
__global__ void k_edge64(const float* __restrict__ g, const float* __restrict__ p,
                         const float* __restrict__ q, const float* __restrict__ batt,
                         float* __restrict__ out, int n) {
    int w    = (blockIdx.x * blockDim.x + threadIdx.x) >> 5;
    int lane = threadIdx.x & 31;
    if (w >= n) return;
    float qi = q[w] + batt[0];
    float a0 = 0.f, a1 = 0.f;
    int beg = d_rowptr[w], end = d_rowptr[w + 1];
    for (int ei = beg; ei < end; ei++) {
        int s = d_col[ei];
        float sc = p[s] + qi;
        sc = sc > 0.f ? sc : 0.01f * sc;  // jax leaky_relu default slope
        a0 += sc * g[s * 64 + lane];
        a1 += sc * g[s * 64 + lane + 32];
    }
    out[w * 64 + lane]      = fmaxf(a0, 0.f);  // relu
    out[w * 64 + lane + 32] = fmaxf(a1, 0.f);
}

// ---------------- conv edge aggregation, 32-wide output (conv2, final) -------
__global__ void k_edge32(const float* __restrict__ g, const float* __restrict__ p,
                         const float* __restrict__ q, const float* __restrict__ batt,
                         float* __restrict__ out, int n) {
    int w    = (blockIdx.x * blockDim.x + threadIdx.x) >> 5;
    int lane = threadIdx.x & 31;
    if (w >= n) return;
    float qi = q[w] + batt[0];
    float a0 = 0.f;
    int beg = d_rowptr[w], end = d_rowptr[w + 1];
    for (int ei = beg; ei < end; ei++) {
        int s = d_col[ei];
        float sc = p[s] + qi;
        sc = sc > 0.f ? sc : 0.01f * sc;
        a0 += sc * g[s * 32 + lane];
    }
    out[w * 32 + lane] = a0;  // no activation on final conv
}

// ---------------- launch ------------------------------------------------------
extern "C" void kernel_launch(void* const* d_in, const int* in_sizes, int n_in,
                              void* d_out, int out_size) {
    const float* x     = (const float*)d_in[0];
    const int*   ei    = (const int*)  d_in[1];
    const float* Watt1 = (const float*)d_in[2];
    const float* batt1 = (const float*)d_in[3];
    const float* Wlin1 = (const float*)d_in[4];
    const float* Watt2 = (const float*)d_in[5];
    const float* batt2 = (const float*)d_in[6];
    const float* Wlin2 = (const float*)d_in[7];

    int n = in_sizes[0] / D;   // 50000
    int e = in_sizes[1] / 2;   // 800000
    const int* src = ei;
    const int* dst = ei + e;

    float *buf0, *buf1, *accp, *gp, *hidp, *g2p, *pp, *qp;
    cudaGetSymbolAddress((void**)&buf0, d_buf0);
    cudaGetSymbolAddress((void**)&buf1, d_buf1);
    cudaGetSymbolAddress((void**)&accp, d_acc);
    cudaGetSymbolAddress((void**)&gp,   d_g);
    cudaGetSymbolAddress((void**)&hidp, d_hid);
    cudaGetSymbolAddress((void**)&g2p,  d_g2);
    cudaGetSymbolAddress((void**)&pp,   d_p);
    cudaGetSymbolAddress((void**)&qp,   d_q);

    const int TB = 256;
    int nblk = (n + TB - 1) / TB;
    int nb512 = (n + 511) / 512;
    int wb = (n * 32 + TB - 1) / TB;   // warp-per-node grids

    // CSR build (per launch; cheap relative to passes)
    k_zero_cnt<<<nblk, TB>>>(n);
    k_count<<<592, TB>>>(dst, e);
    k_scanA<<<nb512, 512>>>(n);
    k_scanB<<<1, 1>>>(nb512);
    k_scanC<<<nblk, TB>>>(n, e);
    k_fill<<<592, TB>>>(src, dst, e);

    // graphSmoothing: acc = x + m(x) + m^2(x) + m^3(x); xs = acc/4 (folded below)
    k_pass<<<wb, TB>>>(x,    buf0, 1, n);
    k_pass<<<wb, TB>>>(buf0, buf1, 0, n);
    k_pass<<<wb, TB>>>(buf1, buf0, 0, n);

    // conv1: node precompute + edge aggregate (scale 0.25 folds xs = acc/4)
    k_gemm<64><<<592, 128>>>(accp, 0.25f, Wlin1, gp, n);
    k_pq<<<wb, TB>>>(accp, 0.25f, Watt1, pp, qp, n);
    k_edge64<<<wb, TB>>>(gp, pp, qp, batt1, hidp, n);

    // conv2
    k_gemm<32><<<592, 128>>>(hidp, 1.0f, Wlin2, g2p, n);
    k_pq<<<wb, TB>>>(hidp, 1.0f, Watt2, pp, qp, n);
    k_edge32<<<wb, TB>>>(g2p, pp, qp, batt2, (float*)d_out, n);
}